// round 16
// baseline (speedup 1.0000x reference)
#include <cuda_runtime.h>
#include <cuda_bf16.h>
#include <cuda_fp16.h>
#include <math.h>
#include <cstdint>

// ---------------- problem constants ----------------
#define BTOK 8192
#define DDIM 1280
#define NEXP 4
#define NCH  20
#define CDIM 64
#define NHEAD 4
#define HDIM 16
#define FFH  256

// ---------------- device scratch (allocation-free) ----------------
__device__ float g_wslot[NEXP * BTOK];      // slot -> combine weight
__device__ int   g_tok[NEXP * BTOK];        // slot -> token id
__device__ int   g_cnt[NEXP];
__device__ int   g_slot[2 * BTOK];          // token -> global slot (e*B + slot)
__device__ int   g_tope[2 * BTOK];
__device__ float g_topw[2 * BTOK];
__device__ __half g_xs[(size_t)NEXP * BTOK * DDIM];  // post-attn residual (slot-major, fp16)
__device__ __half g_hf [(size_t)NEXP * BTOK * DDIM]; // compact hidden, fp16 single
__device__ __half g_pwh[(size_t)NEXP * DDIM * DDIM]; // proj weight fp16 (x64)
__device__ __nv_bfloat16 g_fw1b[NEXP * FFH * CDIM];
__device__ __nv_bfloat16 g_fw2b[NEXP * CDIM * FFH];
__device__ __nv_bfloat16 g_ipwb[NEXP * 3 * CDIM * CDIM];   // 192x64 per expert
__device__ __nv_bfloat16 g_opwb[NEXP * CDIM * CDIM];       // 64x64 per expert
__device__ __half g_y [(size_t)NEXP * BTOK * DDIM];        // per-slot proj output (fp16)

// ---------------- warp MMA helpers ----------------
__device__ __forceinline__ uint32_t smem_u32(const void* p) {
    uint32_t a;
    asm("{ .reg .u64 t; cvta.to.shared.u64 t, %1; cvt.u32.u64 %0, t; }" : "=r"(a) : "l"(p));
    return a;
}
__device__ __forceinline__ void ldm_x4(uint32_t& r0, uint32_t& r1, uint32_t& r2, uint32_t& r3,
                                       uint32_t addr) {
    asm volatile("ldmatrix.sync.aligned.m8n8.x4.shared.b16 {%0,%1,%2,%3}, [%4];"
                 : "=r"(r0), "=r"(r1), "=r"(r2), "=r"(r3) : "r"(addr));
}
__device__ __forceinline__ void mma16816(float* d, const uint32_t* a, const uint32_t* b) {
    asm volatile("mma.sync.aligned.m16n8k16.row.col.f32.bf16.bf16.f32 "
                 "{%0,%1,%2,%3}, {%4,%5,%6,%7}, {%8,%9}, {%0,%1,%2,%3};"
                 : "+f"(d[0]), "+f"(d[1]), "+f"(d[2]), "+f"(d[3])
                 : "r"(a[0]), "r"(a[1]), "r"(a[2]), "r"(a[3]), "r"(b[0]), "r"(b[1]));
}
__device__ __forceinline__ void mma16816h(float* d, const uint32_t* a, const uint32_t* b) {
    asm volatile("mma.sync.aligned.m16n8k16.row.col.f32.f16.f16.f32 "
                 "{%0,%1,%2,%3}, {%4,%5,%6,%7}, {%8,%9}, {%0,%1,%2,%3};"
                 : "+f"(d[0]), "+f"(d[1]), "+f"(d[2]), "+f"(d[3])
                 : "r"(a[0]), "r"(a[1]), "r"(a[2]), "r"(a[3]), "r"(b[0]), "r"(b[1]));
}
__device__ __forceinline__ void cpa16(uint32_t dst, const void* src, int srcsize) {
    asm volatile("cp.async.cg.shared.global [%0], [%1], 16, %2;"
                 :: "r"(dst), "l"(src), "r"(srcsize) : "memory");
}
#define CPA_COMMIT() asm volatile("cp.async.commit_group;" ::: "memory")
#define CPA_WAIT2()  asm volatile("cp.async.wait_group 2;" ::: "memory")

// ---------------- K0: init ----------------
__global__ void k_init() {
    if (threadIdx.x < NEXP) g_cnt[threadIdx.x] = 0;
}

// ---------------- K1: fused pre-kernel: gate(1024 blocks) | convb(256) | convw(6400) ----------------
#define PRE_GATE_BLKS 1024
#define PRE_CONVB_BLKS 256
#define PRE_CONVW_BLKS 6400
#define PRE_TOT_BLKS (PRE_GATE_BLKS + PRE_CONVB_BLKS + PRE_CONVW_BLKS)

__global__ void k_pre(const float* __restrict__ x,
                      const float* __restrict__ gw1, const float* __restrict__ gb1,
                      const float* __restrict__ gw2, const float* __restrict__ gb2,
                      const float* __restrict__ pw,
                      const float* __restrict__ fw1, const float* __restrict__ fw2,
                      const float* __restrict__ ipw, const float* __restrict__ opw) {
    int blk = blockIdx.x;
    if (blk >= PRE_GATE_BLKS) {
        int cb = blk - PRE_GATE_BLKS;
        if (cb < PRE_CONVB_BLKS) {
            int i = cb * 256 + threadIdx.x;
            if (i < NEXP * FFH * CDIM) {
                g_fw1b[i] = __float2bfloat16(fw1[i]);
                g_fw2b[i] = __float2bfloat16(fw2[i]);
            }
            if (i < NEXP * 3 * CDIM * CDIM) g_ipwb[i] = __float2bfloat16(ipw[i]);
            if (i < NEXP * CDIM * CDIM)     g_opwb[i] = __float2bfloat16(opw[i]);
        } else {
            int cw = cb - PRE_CONVB_BLKS;
            size_t i = ((size_t)cw * 256 + threadIdx.x) * 4;
            const size_t TOT = (size_t)NEXP * DDIM * DDIM;
            if (i < TOT) {
                float4 v = *(const float4*)&pw[i];
                __half h0 = __float2half(v.x * 64.f), h1 = __float2half(v.y * 64.f);
                __half h2 = __float2half(v.z * 64.f), h3 = __float2half(v.w * 64.f);
                *(__half2*)&g_pwh[i]     = __half2(h0, h1);
                *(__half2*)&g_pwh[i + 2] = __half2(h2, h3);
            }
        }
        return;
    }
    // ---- gating + routing (gw1 reused across 8 tokens per warp) ----
    __shared__ float s_x[8][DDIM];
    __shared__ float s_h1[8][16];
    int warp = threadIdx.x >> 5, lane = threadIdx.x & 31;
    int b0 = blk * 8;
    {
        const float* xr = x + (size_t)(b0 + warp) * DDIM;
        for (int d = lane; d < DDIM; d += 32) s_x[warp][d] = xr[d];
    }
    __syncthreads();
#pragma unroll
    for (int jj = 0; jj < 2; jj++) {
        int j = warp * 2 + jj;
        float acc[8];
#pragma unroll
        for (int tok = 0; tok < 8; tok++) acc[tok] = 0.f;
        const float* wr = gw1 + j * DDIM;
        for (int d = lane; d < DDIM; d += 32) {
            float w = wr[d];
#pragma unroll
            for (int tok = 0; tok < 8; tok++) acc[tok] += s_x[tok][d] * w;
        }
#pragma unroll
        for (int tok = 0; tok < 8; tok++) {
            float s = acc[tok];
#pragma unroll
            for (int o = 16; o; o >>= 1) s += __shfl_xor_sync(0xffffffffu, s, o);
            if (lane == 0) s_h1[tok][j] = tanhf(s + gb1[j]);
        }
    }
    __syncthreads();
    if (lane == 0) {
        int b = b0 + warp;
        float logits[NEXP];
#pragma unroll
        for (int e = 0; e < NEXP; e++) {
            float s = gb2[e];
#pragma unroll
            for (int j = 0; j < 16; j++) s += s_h1[warp][j] * gw2[e * 16 + j];
            logits[e] = s;
        }
        float m = logits[0];
#pragma unroll
        for (int e = 1; e < NEXP; e++) m = fmaxf(m, logits[e]);
        float p[NEXP], sum = 0.f;
#pragma unroll
        for (int e = 0; e < NEXP; e++) { p[e] = expf(logits[e] - m); sum += p[e]; }
#pragma unroll
        for (int e = 0; e < NEXP; e++) p[e] /= sum;
        int e0 = 0;
#pragma unroll
        for (int e = 1; e < NEXP; e++) if (p[e] > p[e0]) e0 = e;
        int e1 = -1;
#pragma unroll
        for (int e = 0; e < NEXP; e++) {
            if (e == e0) continue;
            if (e1 < 0 || p[e] > p[e1]) e1 = e;
        }
        float den = p[e0] + p[e1] + 1e-6f;
        float w0 = p[e0] / den, w1 = p[e1] / den;
        int s0 = atomicAdd(&g_cnt[e0], 1);
        int s1 = atomicAdd(&g_cnt[e1], 1);
        g_slot[2 * b]     = e0 * BTOK + s0;
        g_slot[2 * b + 1] = e1 * BTOK + s1;
        g_wslot[e0 * BTOK + s0] = w0;
        g_wslot[e1 * BTOK + s1] = w1;
        g_tok[e0 * BTOK + s0] = b;
        g_tok[e1 * BTOK + s1] = b;
        g_tope[2 * b] = e0; g_tope[2 * b + 1] = e1;
        g_topw[2 * b] = w0; g_topw[2 * b + 1] = w1;
    }
}

// ---------------- K2a: k_att — pos + rms1 + attn (all-MMA) + residual ----------------
#define AT_TOK 6
#define QS 200
#define T_QKV  0
#define T_XN   51200
#define T_IPW  69632
#define T_OPW  97280
#define T_IPB  106496
#define T_OPB  107264
#define T_N1G  107520
#define T_LS1  107776
#define T_TOK  108032
#define T_TOT  108064

__global__ void __launch_bounds__(256, 2) k_att(
    const float* __restrict__ x, const float* __restrict__ pos,
    const float* __restrict__ n1g, const float* __restrict__ ipb,
    const float* __restrict__ opb, const float* __restrict__ ls1) {
    int e   = blockIdx.y;
    int tk0 = blockIdx.x * AT_TOK;
    int cnt = g_cnt[e];
    if (tk0 >= cnt) return;
    int nval = min(AT_TOK, cnt - tk0);
    int rows = nval * NCH;

    extern __shared__ char smb[];
    float*         sXS  = (float*)(smb + T_QKV);
    __nv_bfloat16* sQKV = (__nv_bfloat16*)(smb + T_QKV);
    __nv_bfloat16* sXN  = (__nv_bfloat16*)(smb + T_XN);
    __nv_bfloat16* sO   = (__nv_bfloat16*)(smb + T_XN);
    __nv_bfloat16* sIPW = (__nv_bfloat16*)(smb + T_IPW);
    __nv_bfloat16* sOPW = (__nv_bfloat16*)(smb + T_OPW);
    float* sIPB = (float*)(smb + T_IPB);
    float* sOPB = (float*)(smb + T_OPB);
    float* sN1G = (float*)(smb + T_N1G);
    float* sLS1 = (float*)(smb + T_LS1);
    int*   sTok = (int*)(smb + T_TOK);

    int t = threadIdx.x, wid = t >> 5, lane = t & 31;

    if (t < AT_TOK) sTok[t] = (t < nval) ? g_tok[e * BTOK + tk0 + t] : 0;
    __syncthreads();

    {
        const __nv_bfloat16* ipwg = g_ipwb + e * 192 * 64;
        const __nv_bfloat16* opwg = g_opwb + e * 64 * 64;
#pragma unroll
        for (int i = t; i < 1536; i += 256) {
            int j = i >> 3, sg = i & 7;
            *(uint4*)(sIPW + j * 72 + sg * 8) = *(const uint4*)(ipwg + j * 64 + sg * 8);
        }
#pragma unroll
        for (int i = t; i < 512; i += 256) {
            int j = i >> 3, sg = i & 7;
            *(uint4*)(sOPW + j * 72 + sg * 8) = *(const uint4*)(opwg + j * 64 + sg * 8);
        }
#pragma unroll
        for (int i = t; i < 2048; i += 256) {
            int r = i >> 4, q = i & 15;
            float4 v = make_float4(0.f, 0.f, 0.f, 0.f);
            if (r < rows) {
                int tok = sTok[r / NCH], c = r % NCH;
                float4 xv = *(const float4*)(x + (size_t)tok * DDIM + c * 64 + q * 4);
                float4 pv = *(const float4*)(pos + (size_t)e * DDIM + c * 64 + q * 4);
                v = make_float4(xv.x + pv.x, xv.y + pv.y, xv.z + pv.z, xv.w + pv.w);
            }
            *(float4*)(sXS + r * 64 + q * 4) = v;
        }
        if (t < 192) sIPB[t] = ipb[e * 192 + t];
        if (t < 64) {
            sOPB[t] = opb[e * 64 + t];
            sN1G[t] = n1g[e * 64 + t];
            sLS1[t] = ls1[e * 64 + t];
        }
    }
    __syncthreads();

#pragma unroll
    for (int i = 0; i < 16; i++) {
        int r = wid * 16 + i;
        float v0 = sXS[r * 64 + lane], v1 = sXS[r * 64 + 32 + lane];
        float ss = v0 * v0 + v1 * v1;
#pragma unroll
        for (int o = 16; o; o >>= 1) ss += __shfl_xor_sync(0xffffffffu, ss, o);
        float inv = 1.f / (sqrtf(ss * (1.f / 64.f)) + 1e-8f);
        sXN[r * 72 + lane]      = __float2bfloat16(v0 * inv * sN1G[lane]);
        sXN[r * 72 + 32 + lane] = __float2bfloat16(v1 * inv * sN1G[32 + lane]);
    }
    __syncthreads();

    uint32_t sbXN = smem_u32(sXN), sbIPW = smem_u32(sIPW);
    uint32_t sbO  = smem_u32(sO),  sbOPW = smem_u32(sOPW);
    int a_r = (lane & 15), a_k = ((lane >> 4) << 3);
    int b_r = (lane & 7) + ((lane >> 4) << 3), b_k = (((lane >> 3) & 1) << 3);

    {
        int wm4 = wid & 3, wn2 = wid >> 2;
#pragma unroll
        for (int nh = 0; nh < 2; nh++) {
            float acc[2][6][4];
#pragma unroll
            for (int i = 0; i < 2; i++)
#pragma unroll
                for (int j = 0; j < 6; j++)
#pragma unroll
                    for (int q = 0; q < 4; q++) acc[i][j][q] = 0.f;
#pragma unroll
            for (int k16 = 0; k16 < 4; k16++) {
                int kb = k16 * 16;
                uint32_t bh[6][2];
#pragma unroll
                for (int np = 0; np < 3; np++) {
                    uint32_t boff = (uint32_t)((nh * 96 + wn2 * 48 + np * 16 + b_r) * 72 + kb + b_k) * 2;
                    ldm_x4(bh[np * 2][0], bh[np * 2][1], bh[np * 2 + 1][0], bh[np * 2 + 1][1], sbIPW + boff);
                }
#pragma unroll
                for (int mt2 = 0; mt2 < 2; mt2++) {
                    uint32_t aoff = (uint32_t)((wm4 * 32 + mt2 * 16 + a_r) * 72 + kb + a_k) * 2;
                    uint32_t ah[4];
                    ldm_x4(ah[0], ah[1], ah[2], ah[3], sbXN + aoff);
#pragma unroll
                    for (int ntl = 0; ntl < 6; ntl++) mma16816(acc[mt2][ntl], ah, bh[ntl]);
                }
            }
#pragma unroll
            for (int mt2 = 0; mt2 < 2; mt2++) {
#pragma unroll
                for (int ntl = 0; ntl < 6; ntl++) {
                    int col = nh * 96 + wn2 * 48 + ntl * 8 + (lane & 3) * 2;
                    int r1 = wm4 * 32 + mt2 * 16 + (lane >> 2), r2 = r1 + 8;
                    float b0 = sIPB[col], b1 = sIPB[col + 1];
                    *(__nv_bfloat162*)(sQKV + r1 * QS + col) =
                        __float22bfloat162_rn(make_float2(acc[mt2][ntl][0] + b0, acc[mt2][ntl][1] + b1));
                    *(__nv_bfloat162*)(sQKV + r2 * QS + col) =
                        __float22bfloat162_rn(make_float2(acc[mt2][ntl][2] + b0, acc[mt2][ntl][3] + b1));
                }
            }
        }
    }
    __syncthreads();

    for (int task = wid; task < AT_TOK * NHEAD; task += 8) {
        int tk = task >> 2, h = task & 3;
        if (tk >= nval) continue;
        if (lane < NCH) {
            const __nv_bfloat16* qrow = sQKV + (tk * NCH + lane) * QS + h * 16;
            float qv[16];
#pragma unroll
            for (int d2 = 0; d2 < 8; d2++) {
                float2 f = __bfloat1622float2(*(const __nv_bfloat162*)(qrow + d2 * 2));
                qv[d2 * 2] = f.x; qv[d2 * 2 + 1] = f.y;
            }
            float s[NCH];
#pragma unroll
            for (int c2 = 0; c2 < NCH; c2++) {
                const __nv_bfloat16* krow = sQKV + (tk * NCH + c2) * QS + 64 + h * 16;
                float dot = 0.f;
#pragma unroll
                for (int d2 = 0; d2 < 8; d2++) {
                    float2 f = __bfloat1622float2(*(const __nv_bfloat162*)(krow + d2 * 2));
                    dot += qv[d2 * 2] * f.x + qv[d2 * 2 + 1] * f.y;
                }
                s[c2] = dot * 0.25f;
            }
            float m = s[0];
#pragma unroll
            for (int c2 = 1; c2 < NCH; c2++) m = fmaxf(m, s[c2]);
            float sum = 0.f;
#pragma unroll
            for (int c2 = 0; c2 < NCH; c2++) { s[c2] = __expf(s[c2] - m); sum += s[c2]; }
            float inv = 1.f / sum;
            float o[16];
#pragma unroll
            for (int d = 0; d < 16; d++) o[d] = 0.f;
#pragma unroll
            for (int c2 = 0; c2 < NCH; c2++) {
                float a = s[c2] * inv;
                const __nv_bfloat16* vrow = sQKV + (tk * NCH + c2) * QS + 128 + h * 16;
#pragma unroll
                for (int d2 = 0; d2 < 8; d2++) {
                    float2 f = __bfloat1622float2(*(const __nv_bfloat162*)(vrow + d2 * 2));
                    o[d2 * 2] += a * f.x; o[d2 * 2 + 1] += a * f.y;
                }
            }
            __nv_bfloat16* orow = sO + (tk * NCH + lane) * 72 + h * 16;
#pragma unroll
            for (int d2 = 0; d2 < 8; d2++)
                *(__nv_bfloat162*)(orow + d2 * 2) =
                    __float22bfloat162_rn(make_float2(o[d2 * 2], o[d2 * 2 + 1]));
        }
    }
    __syncthreads();

    {
        int wm = wid & 1, wn = wid >> 1;
        float acc[4][2][4];
#pragma unroll
        for (int i = 0; i < 4; i++)
#pragma unroll
            for (int j = 0; j < 2; j++)
#pragma unroll
                for (int q = 0; q < 4; q++) acc[i][j][q] = 0.f;
#pragma unroll
        for (int k16 = 0; k16 < 4; k16++) {
            int kb = k16 * 16;
            uint32_t bh[2][2];
            uint32_t boff = (uint32_t)((wn * 16 + b_r) * 72 + kb + b_k) * 2;
            ldm_x4(bh[0][0], bh[0][1], bh[1][0], bh[1][1], sbOPW + boff);
#pragma unroll
            for (int mt2 = 0; mt2 < 4; mt2++) {
                uint32_t aoff = (uint32_t)((wm * 64 + mt2 * 16 + a_r) * 72 + kb + a_k) * 2;
                uint32_t ah[4];
                ldm_x4(ah[0], ah[1], ah[2], ah[3], sbO + aoff);
#pragma unroll
                for (int ntl = 0; ntl < 2; ntl++) mma16816(acc[mt2][ntl], ah, bh[ntl]);
            }
        }
        __half* gout = g_xs + ((size_t)(e * BTOK + tk0)) * DDIM;
        const float* posE = pos + (size_t)e * DDIM;
#pragma unroll
        for (int mt2 = 0; mt2 < 4; mt2++) {
#pragma unroll
            for (int ntl = 0; ntl < 2; ntl++) {
                int col = wn * 16 + ntl * 8 + (lane & 3) * 2;
                float b0 = sOPB[col], b1 = sOPB[col + 1];
                float l0 = sLS1[col], l1 = sLS1[col + 1];
#pragma unroll
                for (int half = 0; half < 2; half++) {
                    int r = wm * 64 + mt2 * 16 + (lane >> 2) + half * 8;
                    if (r < rows) {
                        int tok = sTok[r / NCH], ch = r % NCH;
                        float2 xv = *(const float2*)(x + (size_t)tok * DDIM + ch * 64 + col);
                        float2 pv = *(const float2*)(posE + ch * 64 + col);
                        float v0 = (xv.x + pv.x) + l0 * (acc[mt2][ntl][half * 2]     + b0);
                        float v1 = (xv.y + pv.y) + l1 * (acc[mt2][ntl][half * 2 + 1] + b1);
                        *(__half2*)(gout + (size_t)r * 64 + col) = __floats2half2_rn(v0, v1);
                    }
                }
            }
        }
    }
}

// ---------------- K2b: warp-MMA FFN (512 threads / 16 warps) ----------------
#define F_XS   0          // 128x64 f32      (32768)
#define F_XN   32768      // 128x72 bf16     (18432)
#define F_F1   51200      // 128x264 bf16    (67584)
#define F_W1   118784     // 256x72 bf16     (36864)
#define F_W2   155648     // 64x264 bf16     (33792)
#define F_N2G  189440
#define F_FB1  189696
#define F_FB2  190720
#define F_LS2  190976
#define F_WGT  191232
#define F_TOT  191744

__global__ void __launch_bounds__(512) k_ffn(
    const float* __restrict__ n2g, const float* __restrict__ fb1,
    const float* __restrict__ fb2, const float* __restrict__ ls2) {
    int e  = blockIdx.y;
    int r0 = blockIdx.x * 128;
    int rows_e = g_cnt[e] * NCH;
    if (r0 >= rows_e) return;

    extern __shared__ char smb[];
    float*          sXS  = (float*)(smb + F_XS);
    __nv_bfloat16*  sXN  = (__nv_bfloat16*)(smb + F_XN);
    __nv_bfloat16*  sF1  = (__nv_bfloat16*)(smb + F_F1);
    __nv_bfloat16*  sW1  = (__nv_bfloat16*)(smb + F_W1);
    __nv_bfloat16*  sW2  = (__nv_bfloat16*)(smb + F_W2);
    float*          sN2G = (float*)(smb + F_N2G);
    float*          sFB1 = (float*)(smb + F_FB1);
    float*          sFB2 = (float*)(smb + F_FB2);
    float*          sLS2 = (float*)(smb + F_LS2);
    float*          sWGT = (float*)(smb + F_WGT);

    int t = threadIdx.x, wid = t >> 5, lane = t & 31;

    {
        const __nv_bfloat16* w1g = g_fw1b + e * FFH * CDIM;
        const __nv_bfloat16* w2g = g_fw2b + e * CDIM * FFH;
        const __half* xsg = g_xs + (size_t)e * BTOK * DDIM + (size_t)r0 * 64;
#pragma unroll
        for (int i = t; i < 2048; i += 512) {
            int j = i >> 3, sg = i & 7;
            *(uint4*)(sW1 + j * 72 + sg * 8) = *(const uint4*)(w1g + j * 64 + sg * 8);
        }
#pragma unroll
        for (int i = t; i < 2048; i += 512) {
            int n = i >> 5, sg = i & 31;
            *(uint4*)(sW2 + n * 264 + sg * 8) = *(const uint4*)(w2g + n * 256 + sg * 8);
        }
#pragma unroll
        for (int i = t; i < 2048; i += 512) {
            int r = i >> 4, sg = i & 15;
            __half2 h01 = *(const __half2*)(xsg + (size_t)r * 64 + sg * 4);
            __half2 h23 = *(const __half2*)(xsg + (size_t)r * 64 + sg * 4 + 2);
            float2 f01 = __half22float2(h01), f23 = __half22float2(h23);
            *(float4*)(sXS + r * 64 + sg * 4) = make_float4(f01.x, f01.y, f23.x, f23.y);
        }
        if (t < 64) { sN2G[t] = n2g[e * 64 + t]; sFB2[t] = fb2[e * 64 + t]; sLS2[t] = ls2[e * 64 + t]; }
        if (t < 256) sFB1[t] = fb1[e * 256 + t];
        if (t >= 256 && t < 384) {
            int rr = r0 + (t - 256);
            sWGT[t - 256] = (rr < rows_e) ? g_wslot[e * BTOK + rr / 20] : 0.f;
        }
    }
    __syncthreads();

#pragma unroll
    for (int i = 0; i < 8; i++) {
        int r = wid * 8 + i;
        float v0 = sXS[r * 64 + lane], v1 = sXS[r * 64 + 32 + lane];
        float ss = v0 * v0 + v1 * v1;
#pragma unroll
        for (int o = 16; o; o >>= 1) ss += __shfl_xor_sync(0xffffffffu, ss, o);
        float inv = 1.f / (sqrtf(ss * (1.f / 64.f)) + 1e-8f);
        sXN[r * 72 + lane]      = __float2bfloat16(v0 * inv * sN2G[lane]);
        sXN[r * 72 + 32 + lane] = __float2bfloat16(v1 * inv * sN2G[32 + lane]);
    }
    __syncthreads();

    uint32_t sbXN = smem_u32(sXN), sbW1 = smem_u32(sW1);
    uint32_t sbF1 = smem_u32(sF1), sbW2 = smem_u32(sW2);
    int a_r = (lane & 15), a_k = ((lane >> 4) << 3);
    int b_r = (lane & 7) + ((lane >> 4) << 3), b_k = (((lane >> 3) & 1) << 3);

    {
        int wm = wid & 3, wn = wid >> 2;
        float acc[2][8][4];
#pragma unroll
        for (int i = 0; i < 2; i++)
#pragma unroll
            for (int j = 0; j < 8; j++)
#pragma unroll
                for (int q = 0; q < 4; q++) acc[i][j][q] = 0.f;
#pragma unroll
        for (int k16 = 0; k16 < 4; k16++) {
            int kb = k16 * 16;
            uint32_t bh[8][2];
#pragma unroll
            for (int np = 0; np < 4; np++) {
                uint32_t boff = (uint32_t)((wn * 64 + np * 16 + b_r) * 72 + kb + b_k) * 2;
                ldm_x4(bh[np * 2][0], bh[np * 2][1], bh[np * 2 + 1][0], bh[np * 2 + 1][1], sbW1 + boff);
            }
#pragma unroll
            for (int mt2 = 0; mt2 < 2; mt2++) {
                uint32_t aoff = (uint32_t)((wm * 32 + mt2 * 16 + a_r) * 72 + kb + a_k) * 2;
                uint32_t ah[4];
                ldm_x4(ah[0], ah[1], ah[2], ah[3], sbXN + aoff);
#pragma unroll
                for (int ntl = 0; ntl < 8; ntl++) mma16816(acc[mt2][ntl], ah, bh[ntl]);
            }
        }
#pragma unroll
        for (int mt2 = 0; mt2 < 2; mt2++) {
#pragma unroll
            for (int ntl = 0; ntl < 8; ntl++) {
                int col = wn * 64 + ntl * 8 + (lane & 3) * 2;
                int r1 = wm * 32 + mt2 * 16 + (lane >> 2), r2 = r1 + 8;
                float b0 = sFB1[col], b1 = sFB1[col + 1];
                float c0 = fmaxf(acc[mt2][ntl][0] + b0, 0.f);
                float c1 = fmaxf(acc[mt2][ntl][1] + b1, 0.f);
                float c2 = fmaxf(acc[mt2][ntl][2] + b0, 0.f);
                float c3 = fmaxf(acc[mt2][ntl][3] + b1, 0.f);
                *(__nv_bfloat162*)(sF1 + r1 * 264 + col) = __float22bfloat162_rn(make_float2(c0, c1));
                *(__nv_bfloat162*)(sF1 + r2 * 264 + col) = __float22bfloat162_rn(make_float2(c2, c3));
            }
        }
    }
    __syncthreads();

    {
        int wm2 = wid & 7, wn2 = wid >> 3;
        float acc2[4][4];
#pragma unroll
        for (int j = 0; j < 4; j++)
#pragma unroll
            for (int q = 0; q < 4; q++) acc2[j][q] = 0.f;
#pragma unroll
        for (int k16 = 0; k16 < 16; k16++) {
            int kb = k16 * 16;
            uint32_t bh[4][2];
#pragma unroll
            for (int np = 0; np < 2; np++) {
                uint32_t boff = (uint32_t)((wn2 * 32 + np * 16 + b_r) * 264 + kb + b_k) * 2;
                ldm_x4(bh[np * 2][0], bh[np * 2][1], bh[np * 2 + 1][0], bh[np * 2 + 1][1], sbW2 + boff);
            }
            uint32_t aoff = (uint32_t)((wm2 * 16 + a_r) * 264 + kb + a_k) * 2;
            uint32_t ah[4];
            ldm_x4(ah[0], ah[1], ah[2], ah[3], sbF1 + aoff);
#pragma unroll
            for (int ntl = 0; ntl < 4; ntl++) mma16816(acc2[ntl], ah, bh[ntl]);
        }
        __half* ghf = g_hf + (size_t)e * BTOK * DDIM + (size_t)r0 * 64;
#pragma unroll
        for (int ntl = 0; ntl < 4; ntl++) {
            int col = wn2 * 32 + ntl * 8 + (lane & 3) * 2;
            float b0 = sFB2[col], b1 = sFB2[col + 1];
            float l0 = sLS2[col], l1 = sLS2[col + 1];
#pragma unroll
            for (int half = 0; half < 2; half++) {
                int r = wm2 * 16 + (lane >> 2) + half * 8;
                if (r0 + r < rows_e) {
                    float w = sWGT[r];
                    float v0 = w * (sXS[r * 64 + col]     + l0 * (acc2[ntl][half * 2]     + b0));
                    float v1 = w * (sXS[r * 64 + col + 1] + l1 * (acc2[ntl][half * 2 + 1] + b1));
                    *(__half2*)(ghf + (size_t)r * 64 + col) = __floats2half2_rn(v0, v1);
                }
            }
        }
    }
}

// ---------------- K3: warp-MMA fp16 proj GEMM, cp.async TRIPLE-buffered ----------------
#define KC 32
#define SSTRIDE 40
#define PJ_TILE_BYTES 10240
#define PJ_STAGE_BYTES (2 * PJ_TILE_BYTES)
#define PJ_SMEM (3 * PJ_STAGE_BYTES)          // 61440: 3 stages

__global__ void __launch_bounds__(256, 2) k_proj_mma() {
    int e  = blockIdx.y >> 6;
    int mt = blockIdx.y & 63;
    int nt = blockIdx.x;
    int cnt = g_cnt[e];
    int row0 = mt * 128;
    if (row0 >= cnt) return;

    extern __shared__ char smb[];
    uint32_t sb0 = smem_u32(smb);

    int t = threadIdx.x;
    int wid = t >> 5, lane = t & 31;
    int wm = wid & 1, wn = wid >> 1;

    const __half* Af = g_hf + (size_t)(e * BTOK) * DDIM;
    const __half* Bf = g_pwh + (size_t)e * DDIM * DDIM + (size_t)(nt * 128) * DDIM;

    float acc[4][4][4];
#pragma unroll
    for (int i = 0; i < 4; i++)
#pragma unroll
        for (int j = 0; j < 4; j++)
#pragma unroll
            for (int q = 0; q < 4; q++) acc[i][j][q] = 0.f;

    int rw0 = t >> 2, q0 = t & 3;
    int rw1 = rw0 + 64, q1 = q0;
    bool v0 = (row0 + rw0) < cnt, v1 = (row0 + rw1) < cnt;
    int ra0 = v0 ? (row0 + rw0) : 0, ra1 = v1 ? (row0 + rw1) : 0;
    int sz0 = v0 ? 16 : 0, sz1 = v1 ? 16 : 0;
    uint32_t off0 = (uint32_t)(rw0 * 5 + q0) * 16;
    uint32_t off1 = (uint32_t)(rw1 * 5 + q1) * 16;

#define PJ_ISSUE(cc, stg) do { \
        int k0 = (cc) * KC; \
        uint32_t db = sb0 + (uint32_t)(stg) * PJ_STAGE_BYTES; \
        size_t ea0 = (size_t)ra0 * DDIM + k0 + q0 * 8; \
        size_t ea1 = (size_t)ra1 * DDIM + k0 + q1 * 8; \
        size_t eb0 = (size_t)rw0 * DDIM + k0 + q0 * 8; \
        size_t eb1 = (size_t)rw1 * DDIM + k0 + q1 * 8; \
        cpa16(db + off0,                 Af + ea0, sz0); \
        cpa16(db + off1,                 Af + ea1, sz1); \
        cpa16(db + PJ_TILE_BYTES + off0, Bf + eb0, 16); \
        cpa16(db + PJ_TILE_BYTES + off1, Bf + eb1, 16); \
    } while (0)

    int a_r = (lane & 15), a_k = ((lane >> 4) << 3);
    int b_r = (lane & 7) + ((lane >> 4) << 3), b_k = (((lane >> 3) & 1) << 3);

    const int NCHUNK = DDIM / KC;   // 40
    PJ_ISSUE(0, 0); CPA_COMMIT();
    PJ_ISSUE(1, 1); CPA_COMMIT();
    PJ_ISSUE(2, 2); CPA_COMMIT();

    int stg = 0;
    for (int c = 0; c < NCHUNK; c++) {
        CPA_WAIT2();                 // chunk c resident (2 groups may remain in flight)
        __syncthreads();
        uint32_t base = sb0 + (uint32_t)stg * PJ_STAGE_BYTES;
        uint32_t sA = base, sB = base + PJ_TILE_BYTES;

#pragma unroll
        for (int k16 = 0; k16 < 2; k16++) {
            int kb = k16 * 16;
            uint32_t bh[4][2];
#pragma unroll
            for (int np = 0; np < 2; np++) {
                uint32_t boff = (uint32_t)((wn * 32 + np * 16 + b_r) * SSTRIDE + kb + b_k) * 2;
                ldm_x4(bh[np * 2][0], bh[np * 2][1], bh[np * 2 + 1][0], bh[np * 2 + 1][1], sB + boff);
            }
#pragma unroll
            for (int mt2 = 0; mt2 < 4; mt2++) {
                uint32_t aoff = (uint32_t)((wm * 64 + mt2 * 16 + a_r) * SSTRIDE + kb + a_k) * 2;
                uint32_t ah[4];
                ldm_x4(ah[0], ah[1], ah[2], ah[3], sA + aoff);
#pragma unroll
                for (int ntl = 0; ntl < 4; ntl++)
                    mma16816h(acc[mt2][ntl], ah, bh[ntl]);
            }
        }
        __syncthreads();             // all reads of this stage done before refill
        if (c + 3 < NCHUNK) PJ_ISSUE(c + 3, stg);
        CPA_COMMIT();                // exactly one group per iteration (may be empty)
        stg = (stg == 2) ? 0 : stg + 1;
    }

    const float SCL = 1.f / 64.f;
    int lrow = lane >> 2, lcol = (lane & 3) * 2;
    __half* Ybase = g_y + (size_t)(e * BTOK) * DDIM;
#pragma unroll
    for (int mt2 = 0; mt2 < 4; mt2++) {
        int rbase = row0 + wm * 64 + mt2 * 16;
        int r1 = rbase + lrow, r2 = rbase + 8 + lrow;
#pragma unroll
        for (int ntl = 0; ntl < 4; ntl++) {
            int col = nt * 128 + wn * 32 + ntl * 8 + lcol;
            if (r1 < cnt) {
                *(__half2*)&Ybase[(size_t)r1 * DDIM + col] =
                    __floats2half2_rn(acc[mt2][ntl][0] * SCL, acc[mt2][ntl][1] * SCL);
            }
            if (r2 < cnt) {
                *(__half2*)&Ybase[(size_t)r2 * DDIM + col] =
                    __floats2half2_rn(acc[mt2][ntl][2] * SCL, acc[mt2][ntl][3] * SCL);
            }
        }
    }
}

// ---------------- K4: combine (+bias) + aux/load tail, 4 elems/thread ----------------
__global__ void k_combine(const float* __restrict__ pb, float* __restrict__ out,
                          long long out_size) {
    long long idx = (long long)blockIdx.x * 256 + threadIdx.x;
    const long long TOT4 = (long long)BTOK * DDIM / 4;
    if (idx < TOT4) {
        int b = (int)(idx / (DDIM / 4));
        int d = (int)(idx % (DDIM / 4)) * 4;
        int s0 = g_slot[2 * b], s1 = g_slot[2 * b + 1];
        int e0 = g_tope[2 * b], e1 = g_tope[2 * b + 1];
        float w0 = g_topw[2 * b], w1 = g_topw[2 * b + 1];
        const __half2* y0 = (const __half2*)(g_y + (size_t)s0 * DDIM + d);
        const __half2* y1 = (const __half2*)(g_y + (size_t)s1 * DDIM + d);
        float2 a0 = __half22float2(y0[0]), a1 = __half22float2(y0[1]);
        float2 b0 = __half22float2(y1[0]), b1 = __half22float2(y1[1]);
        float4 p0 = *(const float4*)(pb + (size_t)e0 * DDIM + d);
        float4 p1 = *(const float4*)(pb + (size_t)e1 * DDIM + d);
        float4 r;
        r.x = a0.x + b0.x + w0 * p0.x + w1 * p1.x;
        r.y = a0.y + b0.y + w0 * p0.y + w1 * p1.y;
        r.z = a1.x + b1.x + w0 * p0.z + w1 * p1.z;
        r.w = a1.y + b1.y + w0 * p0.w + w1 * p1.w;
        *(float4*)(out + idx * 4) = r;
    }
    if (idx == 0) {
        const long long TOT = (long long)BTOK * DDIM;
        if (out_size >= TOT + 5) {
            out[TOT] = 0.f;
#pragma unroll
            for (int e = 0; e < NEXP; e++) out[TOT + 1 + e] = (float)g_cnt[e];
        }
    }
}

// ---------------- host launcher ----------------
extern "C" void kernel_launch(void* const* d_in, const int* in_sizes, int n_in,
                              void* d_out, int out_size) {
    const float* x    = (const float*)d_in[0];
    const float* gw1  = (const float*)d_in[1];
    const float* gb1  = (const float*)d_in[2];
    const float* gw2  = (const float*)d_in[3];
    const float* gb2  = (const float*)d_in[4];
    const float* pos  = (const float*)d_in[5];
    const float* n1g  = (const float*)d_in[6];
    const float* ipw  = (const float*)d_in[7];
    const float* ipb  = (const float*)d_in[8];
    const float* opw  = (const float*)d_in[9];
    const float* opb  = (const float*)d_in[10];
    const float* ls1  = (const float*)d_in[11];
    const float* n2g  = (const float*)d_in[12];
    const float* fw1  = (const float*)d_in[13];
    const float* fb1  = (const float*)d_in[14];
    const float* fw2  = (const float*)d_in[15];
    const float* fb2  = (const float*)d_in[16];
    const float* ls2  = (const float*)d_in[17];
    const float* pw   = (const float*)d_in[18];
    const float* pb   = (const float*)d_in[19];
    float* out = (float*)d_out;

    cudaFuncSetAttribute(k_att, cudaFuncAttributeMaxDynamicSharedMemorySize, T_TOT);
    cudaFuncSetAttribute(k_ffn, cudaFuncAttributeMaxDynamicSharedMemorySize, F_TOT);
    cudaFuncSetAttribute(k_proj_mma, cudaFuncAttributeMaxDynamicSharedMemorySize, PJ_SMEM);

    k_init<<<1, 32>>>();
    k_pre<<<PRE_TOT_BLKS, 256>>>(x, gw1, gb1, gw2, gb2, pw, fw1, fw2, ipw, opw);
    k_att<<<dim3((BTOK + AT_TOK - 1) / AT_TOK, NEXP), 256, T_TOT>>>(x, pos, n1g, ipb, opb, ls1);
    k_ffn<<<dim3(BTOK * NCH / 128, NEXP), 512, F_TOT>>>(n2g, fb1, fb2, ls2);
    k_proj_mma<<<dim3(DDIM / 128, NEXP * 64), 256, PJ_SMEM>>>();
    long long tot4 = (long long)BTOK * DDIM / 4;
    k_combine<<<(unsigned)((tot4 + 255) / 256), 256>>>(pb, out, (long long)out_size);
}

// round 17
// speedup vs baseline: 1.0221x; 1.0221x over previous
#include <cuda_runtime.h>
#include <cuda_bf16.h>
#include <cuda_fp16.h>
#include <math.h>
#include <cstdint>

// ---------------- problem constants ----------------
#define BTOK 8192
#define DDIM 1280
#define NEXP 4
#define NCH  20
#define CDIM 64
#define NHEAD 4
#define HDIM 16
#define FFH  256

// ---------------- device scratch (allocation-free) ----------------
__device__ float g_wslot[NEXP * BTOK];      // slot -> combine weight
__device__ int   g_tok[NEXP * BTOK];        // slot -> token id
__device__ int   g_cnt[NEXP];
__device__ int   g_slot[2 * BTOK];          // token -> global slot (e*B + slot)
__device__ int   g_tope[2 * BTOK];
__device__ float g_topw[2 * BTOK];
__device__ __half g_xs[(size_t)NEXP * BTOK * DDIM];  // post-attn residual (slot-major, fp16)
__device__ __half g_hf [(size_t)NEXP * BTOK * DDIM]; // compact hidden, fp16 single
__device__ __half g_pwh[(size_t)NEXP * DDIM * DDIM]; // proj weight fp16 (x64)
__device__ __nv_bfloat16 g_fw1b[NEXP * FFH * CDIM];
__device__ __nv_bfloat16 g_fw2b[NEXP * CDIM * FFH];
__device__ __nv_bfloat16 g_ipwb[NEXP * 3 * CDIM * CDIM];   // 192x64 per expert
__device__ __nv_bfloat16 g_opwb[NEXP * CDIM * CDIM];       // 64x64 per expert
__device__ __half g_y [(size_t)NEXP * BTOK * DDIM];        // per-slot proj output (fp16)

// ---------------- warp MMA helpers ----------------
__device__ __forceinline__ uint32_t smem_u32(const void* p) {
    uint32_t a;
    asm("{ .reg .u64 t; cvta.to.shared.u64 t, %1; cvt.u32.u64 %0, t; }" : "=r"(a) : "l"(p));
    return a;
}
__device__ __forceinline__ void ldm_x4(uint32_t& r0, uint32_t& r1, uint32_t& r2, uint32_t& r3,
                                       uint32_t addr) {
    asm volatile("ldmatrix.sync.aligned.m8n8.x4.shared.b16 {%0,%1,%2,%3}, [%4];"
                 : "=r"(r0), "=r"(r1), "=r"(r2), "=r"(r3) : "r"(addr));
}
__device__ __forceinline__ void mma16816(float* d, const uint32_t* a, const uint32_t* b) {
    asm volatile("mma.sync.aligned.m16n8k16.row.col.f32.bf16.bf16.f32 "
                 "{%0,%1,%2,%3}, {%4,%5,%6,%7}, {%8,%9}, {%0,%1,%2,%3};"
                 : "+f"(d[0]), "+f"(d[1]), "+f"(d[2]), "+f"(d[3])
                 : "r"(a[0]), "r"(a[1]), "r"(a[2]), "r"(a[3]), "r"(b[0]), "r"(b[1]));
}
__device__ __forceinline__ void mma16816h(float* d, const uint32_t* a, const uint32_t* b) {
    asm volatile("mma.sync.aligned.m16n8k16.row.col.f32.f16.f16.f32 "
                 "{%0,%1,%2,%3}, {%4,%5,%6,%7}, {%8,%9}, {%0,%1,%2,%3};"
                 : "+f"(d[0]), "+f"(d[1]), "+f"(d[2]), "+f"(d[3])
                 : "r"(a[0]), "r"(a[1]), "r"(a[2]), "r"(a[3]), "r"(b[0]), "r"(b[1]));
}
__device__ __forceinline__ void cpa16(uint32_t dst, const void* src, int srcsize) {
    asm volatile("cp.async.cg.shared.global [%0], [%1], 16, %2;"
                 :: "r"(dst), "l"(src), "r"(srcsize) : "memory");
}
#define CPA_COMMIT() asm volatile("cp.async.commit_group;" ::: "memory")
#define CPA_WAIT1()  asm volatile("cp.async.wait_group 1;" ::: "memory")

// ---------------- K0: init ----------------
__global__ void k_init() {
    if (threadIdx.x < NEXP) g_cnt[threadIdx.x] = 0;
}

// ---------------- K1: fused pre-kernel: gate(1024 blocks) | convb(256) | convw(6400) ----------------
#define PRE_GATE_BLKS 1024
#define PRE_CONVB_BLKS 256
#define PRE_CONVW_BLKS 6400
#define PRE_TOT_BLKS (PRE_GATE_BLKS + PRE_CONVB_BLKS + PRE_CONVW_BLKS)

__global__ void k_pre(const float* __restrict__ x,
                      const float* __restrict__ gw1, const float* __restrict__ gb1,
                      const float* __restrict__ gw2, const float* __restrict__ gb2,
                      const float* __restrict__ pw,
                      const float* __restrict__ fw1, const float* __restrict__ fw2,
                      const float* __restrict__ ipw, const float* __restrict__ opw) {
    int blk = blockIdx.x;
    if (blk >= PRE_GATE_BLKS) {
        int cb = blk - PRE_GATE_BLKS;
        if (cb < PRE_CONVB_BLKS) {
            int i = cb * 256 + threadIdx.x;
            if (i < NEXP * FFH * CDIM) {
                g_fw1b[i] = __float2bfloat16(fw1[i]);
                g_fw2b[i] = __float2bfloat16(fw2[i]);
            }
            if (i < NEXP * 3 * CDIM * CDIM) g_ipwb[i] = __float2bfloat16(ipw[i]);
            if (i < NEXP * CDIM * CDIM)     g_opwb[i] = __float2bfloat16(opw[i]);
        } else {
            int cw = cb - PRE_CONVB_BLKS;
            size_t i = ((size_t)cw * 256 + threadIdx.x) * 4;
            const size_t TOT = (size_t)NEXP * DDIM * DDIM;
            if (i < TOT) {
                float4 v = *(const float4*)&pw[i];
                __half h0 = __float2half(v.x * 64.f), h1 = __float2half(v.y * 64.f);
                __half h2 = __float2half(v.z * 64.f), h3 = __float2half(v.w * 64.f);
                *(__half2*)&g_pwh[i]     = __half2(h0, h1);
                *(__half2*)&g_pwh[i + 2] = __half2(h2, h3);
            }
        }
        return;
    }
    // ---- gating + routing (gw1 reused across 8 tokens per warp) ----
    __shared__ float s_x[8][DDIM];
    __shared__ float s_h1[8][16];
    int warp = threadIdx.x >> 5, lane = threadIdx.x & 31;
    int b0 = blk * 8;
    {
        const float* xr = x + (size_t)(b0 + warp) * DDIM;
        for (int d = lane; d < DDIM; d += 32) s_x[warp][d] = xr[d];
    }
    __syncthreads();
#pragma unroll
    for (int jj = 0; jj < 2; jj++) {
        int j = warp * 2 + jj;
        float acc[8];
#pragma unroll
        for (int tok = 0; tok < 8; tok++) acc[tok] = 0.f;
        const float* wr = gw1 + j * DDIM;
        for (int d = lane; d < DDIM; d += 32) {
            float w = wr[d];
#pragma unroll
            for (int tok = 0; tok < 8; tok++) acc[tok] += s_x[tok][d] * w;
        }
#pragma unroll
        for (int tok = 0; tok < 8; tok++) {
            float s = acc[tok];
#pragma unroll
            for (int o = 16; o; o >>= 1) s += __shfl_xor_sync(0xffffffffu, s, o);
            if (lane == 0) s_h1[tok][j] = tanhf(s + gb1[j]);
        }
    }
    __syncthreads();
    if (lane == 0) {
        int b = b0 + warp;
        float logits[NEXP];
#pragma unroll
        for (int e = 0; e < NEXP; e++) {
            float s = gb2[e];
#pragma unroll
            for (int j = 0; j < 16; j++) s += s_h1[warp][j] * gw2[e * 16 + j];
            logits[e] = s;
        }
        float m = logits[0];
#pragma unroll
        for (int e = 1; e < NEXP; e++) m = fmaxf(m, logits[e]);
        float p[NEXP], sum = 0.f;
#pragma unroll
        for (int e = 0; e < NEXP; e++) { p[e] = expf(logits[e] - m); sum += p[e]; }
#pragma unroll
        for (int e = 0; e < NEXP; e++) p[e] /= sum;
        int e0 = 0;
#pragma unroll
        for (int e = 1; e < NEXP; e++) if (p[e] > p[e0]) e0 = e;
        int e1 = -1;
#pragma unroll
        for (int e = 0; e < NEXP; e++) {
            if (e == e0) continue;
            if (e1 < 0 || p[e] > p[e1]) e1 = e;
        }
        float den = p[e0] + p[e1] + 1e-6f;
        float w0 = p[e0] / den, w1 = p[e1] / den;
        int s0 = atomicAdd(&g_cnt[e0], 1);
        int s1 = atomicAdd(&g_cnt[e1], 1);
        g_slot[2 * b]     = e0 * BTOK + s0;
        g_slot[2 * b + 1] = e1 * BTOK + s1;
        g_wslot[e0 * BTOK + s0] = w0;
        g_wslot[e1 * BTOK + s1] = w1;
        g_tok[e0 * BTOK + s0] = b;
        g_tok[e1 * BTOK + s1] = b;
        g_tope[2 * b] = e0; g_tope[2 * b + 1] = e1;
        g_topw[2 * b] = w0; g_topw[2 * b + 1] = w1;
    }
}

// ---------------- K2a: k_att — pos + rms1 + attn (all-MMA) + residual ----------------
#define AT_TOK 6
#define QS 200
#define T_QKV  0
#define T_XN   51200
#define T_IPW  69632
#define T_OPW  97280
#define T_IPB  106496
#define T_OPB  107264
#define T_N1G  107520
#define T_LS1  107776
#define T_TOK  108032
#define T_TOT  108064

__global__ void __launch_bounds__(256, 2) k_att(
    const float* __restrict__ x, const float* __restrict__ pos,
    const float* __restrict__ n1g, const float* __restrict__ ipb,
    const float* __restrict__ opb, const float* __restrict__ ls1) {
    int e   = blockIdx.y;
    int tk0 = blockIdx.x * AT_TOK;
    int cnt = g_cnt[e];
    if (tk0 >= cnt) return;
    int nval = min(AT_TOK, cnt - tk0);
    int rows = nval * NCH;

    extern __shared__ char smb[];
    float*         sXS  = (float*)(smb + T_QKV);
    __nv_bfloat16* sQKV = (__nv_bfloat16*)(smb + T_QKV);
    __nv_bfloat16* sXN  = (__nv_bfloat16*)(smb + T_XN);
    __nv_bfloat16* sO   = (__nv_bfloat16*)(smb + T_XN);
    __nv_bfloat16* sIPW = (__nv_bfloat16*)(smb + T_IPW);
    __nv_bfloat16* sOPW = (__nv_bfloat16*)(smb + T_OPW);
    float* sIPB = (float*)(smb + T_IPB);
    float* sOPB = (float*)(smb + T_OPB);
    float* sN1G = (float*)(smb + T_N1G);
    float* sLS1 = (float*)(smb + T_LS1);
    int*   sTok = (int*)(smb + T_TOK);

    int t = threadIdx.x, wid = t >> 5, lane = t & 31;

    if (t < AT_TOK) sTok[t] = (t < nval) ? g_tok[e * BTOK + tk0 + t] : 0;
    __syncthreads();

    __half* gxsb = g_xs + ((size_t)(e * BTOK + tk0)) * DDIM;   // this block's slot rows
    {
        const __nv_bfloat16* ipwg = g_ipwb + e * 192 * 64;
        const __nv_bfloat16* opwg = g_opwb + e * 64 * 64;
#pragma unroll
        for (int i = t; i < 1536; i += 256) {
            int j = i >> 3, sg = i & 7;
            *(uint4*)(sIPW + j * 72 + sg * 8) = *(const uint4*)(ipwg + j * 64 + sg * 8);
        }
#pragma unroll
        for (int i = t; i < 512; i += 256) {
            int j = i >> 3, sg = i & 7;
            *(uint4*)(sOPW + j * 72 + sg * 8) = *(const uint4*)(opwg + j * 64 + sg * 8);
        }
#pragma unroll
        for (int i = t; i < 2048; i += 256) {
            int r = i >> 4, q = i & 15;
            float4 v = make_float4(0.f, 0.f, 0.f, 0.f);
            if (r < rows) {
                int tok = sTok[r / NCH], c = r % NCH;
                float4 xv = *(const float4*)(x + (size_t)tok * DDIM + c * 64 + q * 4);
                float4 pv = *(const float4*)(pos + (size_t)e * DDIM + c * 64 + q * 4);
                v = make_float4(xv.x + pv.x, xv.y + pv.y, xv.z + pv.z, xv.w + pv.w);
                // pre-write fp16 xs for the epilogue's residual re-read (overwritten later)
                *(__half2*)(gxsb + (size_t)r * 64 + q * 4)     = __floats2half2_rn(v.x, v.y);
                *(__half2*)(gxsb + (size_t)r * 64 + q * 4 + 2) = __floats2half2_rn(v.z, v.w);
            }
            *(float4*)(sXS + r * 64 + q * 4) = v;
        }
        if (t < 192) sIPB[t] = ipb[e * 192 + t];
        if (t < 64) {
            sOPB[t] = opb[e * 64 + t];
            sN1G[t] = n1g[e * 64 + t];
            sLS1[t] = ls1[e * 64 + t];
        }
    }
    __syncthreads();

#pragma unroll
    for (int i = 0; i < 16; i++) {
        int r = wid * 16 + i;
        float v0 = sXS[r * 64 + lane], v1 = sXS[r * 64 + 32 + lane];
        float ss = v0 * v0 + v1 * v1;
#pragma unroll
        for (int o = 16; o; o >>= 1) ss += __shfl_xor_sync(0xffffffffu, ss, o);
        float inv = 1.f / (sqrtf(ss * (1.f / 64.f)) + 1e-8f);
        sXN[r * 72 + lane]      = __float2bfloat16(v0 * inv * sN1G[lane]);
        sXN[r * 72 + 32 + lane] = __float2bfloat16(v1 * inv * sN1G[32 + lane]);
    }
    __syncthreads();

    uint32_t sbXN = smem_u32(sXN), sbIPW = smem_u32(sIPW);
    uint32_t sbO  = smem_u32(sO),  sbOPW = smem_u32(sOPW);
    int a_r = (lane & 15), a_k = ((lane >> 4) << 3);
    int b_r = (lane & 7) + ((lane >> 4) << 3), b_k = (((lane >> 3) & 1) << 3);

    {
        int wm4 = wid & 3, wn2 = wid >> 2;
#pragma unroll
        for (int nh = 0; nh < 2; nh++) {
            float acc[2][6][4];
#pragma unroll
            for (int i = 0; i < 2; i++)
#pragma unroll
                for (int j = 0; j < 6; j++)
#pragma unroll
                    for (int q = 0; q < 4; q++) acc[i][j][q] = 0.f;
#pragma unroll
            for (int k16 = 0; k16 < 4; k16++) {
                int kb = k16 * 16;
                uint32_t bh[6][2];
#pragma unroll
                for (int np = 0; np < 3; np++) {
                    uint32_t boff = (uint32_t)((nh * 96 + wn2 * 48 + np * 16 + b_r) * 72 + kb + b_k) * 2;
                    ldm_x4(bh[np * 2][0], bh[np * 2][1], bh[np * 2 + 1][0], bh[np * 2 + 1][1], sbIPW + boff);
                }
#pragma unroll
                for (int mt2 = 0; mt2 < 2; mt2++) {
                    uint32_t aoff = (uint32_t)((wm4 * 32 + mt2 * 16 + a_r) * 72 + kb + a_k) * 2;
                    uint32_t ah[4];
                    ldm_x4(ah[0], ah[1], ah[2], ah[3], sbXN + aoff);
#pragma unroll
                    for (int ntl = 0; ntl < 6; ntl++) mma16816(acc[mt2][ntl], ah, bh[ntl]);
                }
            }
#pragma unroll
            for (int mt2 = 0; mt2 < 2; mt2++) {
#pragma unroll
                for (int ntl = 0; ntl < 6; ntl++) {
                    int col = nh * 96 + wn2 * 48 + ntl * 8 + (lane & 3) * 2;
                    int r1 = wm4 * 32 + mt2 * 16 + (lane >> 2), r2 = r1 + 8;
                    float b0 = sIPB[col], b1 = sIPB[col + 1];
                    *(__nv_bfloat162*)(sQKV + r1 * QS + col) =
                        __float22bfloat162_rn(make_float2(acc[mt2][ntl][0] + b0, acc[mt2][ntl][1] + b1));
                    *(__nv_bfloat162*)(sQKV + r2 * QS + col) =
                        __float22bfloat162_rn(make_float2(acc[mt2][ntl][2] + b0, acc[mt2][ntl][3] + b1));
                }
            }
        }
    }
    __syncthreads();

    for (int task = wid; task < AT_TOK * NHEAD; task += 8) {
        int tk = task >> 2, h = task & 3;
        if (tk >= nval) continue;
        if (lane < NCH) {
            const __nv_bfloat16* qrow = sQKV + (tk * NCH + lane) * QS + h * 16;
            float qv[16];
#pragma unroll
            for (int d2 = 0; d2 < 8; d2++) {
                float2 f = __bfloat1622float2(*(const __nv_bfloat162*)(qrow + d2 * 2));
                qv[d2 * 2] = f.x; qv[d2 * 2 + 1] = f.y;
            }
            float s[NCH];
#pragma unroll
            for (int c2 = 0; c2 < NCH; c2++) {
                const __nv_bfloat16* krow = sQKV + (tk * NCH + c2) * QS + 64 + h * 16;
                float dot = 0.f;
#pragma unroll
                for (int d2 = 0; d2 < 8; d2++) {
                    float2 f = __bfloat1622float2(*(const __nv_bfloat162*)(krow + d2 * 2));
                    dot += qv[d2 * 2] * f.x + qv[d2 * 2 + 1] * f.y;
                }
                s[c2] = dot * 0.25f;
            }
            float m = s[0];
#pragma unroll
            for (int c2 = 1; c2 < NCH; c2++) m = fmaxf(m, s[c2]);
            float sum = 0.f;
#pragma unroll
            for (int c2 = 0; c2 < NCH; c2++) { s[c2] = __expf(s[c2] - m); sum += s[c2]; }
            float inv = 1.f / sum;
            float o[16];
#pragma unroll
            for (int d = 0; d < 16; d++) o[d] = 0.f;
#pragma unroll
            for (int c2 = 0; c2 < NCH; c2++) {
                float a = s[c2] * inv;
                const __nv_bfloat16* vrow = sQKV + (tk * NCH + c2) * QS + 128 + h * 16;
#pragma unroll
                for (int d2 = 0; d2 < 8; d2++) {
                    float2 f = __bfloat1622float2(*(const __nv_bfloat162*)(vrow + d2 * 2));
                    o[d2 * 2] += a * f.x; o[d2 * 2 + 1] += a * f.y;
                }
            }
            __nv_bfloat16* orow = sO + (tk * NCH + lane) * 72 + h * 16;
#pragma unroll
            for (int d2 = 0; d2 < 8; d2++)
                *(__nv_bfloat162*)(orow + d2 * 2) =
                    __float22bfloat162_rn(make_float2(o[d2 * 2], o[d2 * 2 + 1]));
        }
    }
    __syncthreads();

    {
        int wm = wid & 1, wn = wid >> 1;
        float acc[4][2][4];
#pragma unroll
        for (int i = 0; i < 4; i++)
#pragma unroll
            for (int j = 0; j < 2; j++)
#pragma unroll
                for (int q = 0; q < 4; q++) acc[i][j][q] = 0.f;
#pragma unroll
        for (int k16 = 0; k16 < 4; k16++) {
            int kb = k16 * 16;
            uint32_t bh[2][2];
            uint32_t boff = (uint32_t)((wn * 16 + b_r) * 72 + kb + b_k) * 2;
            ldm_x4(bh[0][0], bh[0][1], bh[1][0], bh[1][1], sbOPW + boff);
#pragma unroll
            for (int mt2 = 0; mt2 < 4; mt2++) {
                uint32_t aoff = (uint32_t)((wm * 64 + mt2 * 16 + a_r) * 72 + kb + a_k) * 2;
                uint32_t ah[4];
                ldm_x4(ah[0], ah[1], ah[2], ah[3], sbO + aoff);
#pragma unroll
                for (int ntl = 0; ntl < 2; ntl++) mma16816(acc[mt2][ntl], ah, bh[ntl]);
            }
        }
#pragma unroll
        for (int mt2 = 0; mt2 < 4; mt2++) {
#pragma unroll
            for (int ntl = 0; ntl < 2; ntl++) {
                int col = wn * 16 + ntl * 8 + (lane & 3) * 2;
                float b0 = sOPB[col], b1 = sOPB[col + 1];
                float l0 = sLS1[col], l1 = sLS1[col + 1];
#pragma unroll
                for (int half = 0; half < 2; half++) {
                    int r = wm * 64 + mt2 * 16 + (lane >> 2) + half * 8;
                    if (r < rows) {
                        float2 xv = __half22float2(*(const __half2*)(gxsb + (size_t)r * 64 + col));
                        float v0 = xv.x + l0 * (acc[mt2][ntl][half * 2]     + b0);
                        float v1 = xv.y + l1 * (acc[mt2][ntl][half * 2 + 1] + b1);
                        *(__half2*)(gxsb + (size_t)r * 64 + col) = __floats2half2_rn(v0, v1);
                    }
                }
            }
        }
    }
}

// ---------------- K2b: warp-MMA FFN (512 threads / 16 warps) ----------------
#define F_XS   0          // 128x64 f32      (32768)
#define F_XN   32768      // 128x72 bf16     (18432)
#define F_F1   51200      // 128x264 bf16    (67584)
#define F_W1   118784     // 256x72 bf16     (36864)
#define F_W2   155648     // 64x264 bf16     (33792)
#define F_N2G  189440
#define F_FB1  189696
#define F_FB2  190720
#define F_LS2  190976
#define F_WGT  191232
#define F_TOT  191744

__global__ void __launch_bounds__(512) k_ffn(
    const float* __restrict__ n2g, const float* __restrict__ fb1,
    const float* __restrict__ fb2, const float* __restrict__ ls2) {
    int e  = blockIdx.y;
    int r0 = blockIdx.x * 128;
    int rows_e = g_cnt[e] * NCH;
    if (r0 >= rows_e) return;

    extern __shared__ char smb[];
    float*          sXS  = (float*)(smb + F_XS);
    __nv_bfloat16*  sXN  = (__nv_bfloat16*)(smb + F_XN);
    __nv_bfloat16*  sF1  = (__nv_bfloat16*)(smb + F_F1);
    __nv_bfloat16*  sW1  = (__nv_bfloat16*)(smb + F_W1);
    __nv_bfloat16*  sW2  = (__nv_bfloat16*)(smb + F_W2);
    float*          sN2G = (float*)(smb + F_N2G);
    float*          sFB1 = (float*)(smb + F_FB1);
    float*          sFB2 = (float*)(smb + F_FB2);
    float*          sLS2 = (float*)(smb + F_LS2);
    float*          sWGT = (float*)(smb + F_WGT);

    int t = threadIdx.x, wid = t >> 5, lane = t & 31;

    {
        const __nv_bfloat16* w1g = g_fw1b + e * FFH * CDIM;
        const __nv_bfloat16* w2g = g_fw2b + e * CDIM * FFH;
        const __half* xsg = g_xs + (size_t)e * BTOK * DDIM + (size_t)r0 * 64;
#pragma unroll
        for (int i = t; i < 2048; i += 512) {
            int j = i >> 3, sg = i & 7;
            *(uint4*)(sW1 + j * 72 + sg * 8) = *(const uint4*)(w1g + j * 64 + sg * 8);
        }
#pragma unroll
        for (int i = t; i < 2048; i += 512) {
            int n = i >> 5, sg = i & 31;
            *(uint4*)(sW2 + n * 264 + sg * 8) = *(const uint4*)(w2g + n * 256 + sg * 8);
        }
#pragma unroll
        for (int i = t; i < 2048; i += 512) {
            int r = i >> 4, sg = i & 15;
            __half2 h01 = *(const __half2*)(xsg + (size_t)r * 64 + sg * 4);
            __half2 h23 = *(const __half2*)(xsg + (size_t)r * 64 + sg * 4 + 2);
            float2 f01 = __half22float2(h01), f23 = __half22float2(h23);
            *(float4*)(sXS + r * 64 + sg * 4) = make_float4(f01.x, f01.y, f23.x, f23.y);
        }
        if (t < 64) { sN2G[t] = n2g[e * 64 + t]; sFB2[t] = fb2[e * 64 + t]; sLS2[t] = ls2[e * 64 + t]; }
        if (t < 256) sFB1[t] = fb1[e * 256 + t];
        if (t >= 256 && t < 384) {
            int rr = r0 + (t - 256);
            sWGT[t - 256] = (rr < rows_e) ? g_wslot[e * BTOK + rr / 20] : 0.f;
        }
    }
    __syncthreads();

#pragma unroll
    for (int i = 0; i < 8; i++) {
        int r = wid * 8 + i;
        float v0 = sXS[r * 64 + lane], v1 = sXS[r * 64 + 32 + lane];
        float ss = v0 * v0 + v1 * v1;
#pragma unroll
        for (int o = 16; o; o >>= 1) ss += __shfl_xor_sync(0xffffffffu, ss, o);
        float inv = 1.f / (sqrtf(ss * (1.f / 64.f)) + 1e-8f);
        sXN[r * 72 + lane]      = __float2bfloat16(v0 * inv * sN2G[lane]);
        sXN[r * 72 + 32 + lane] = __float2bfloat16(v1 * inv * sN2G[32 + lane]);
    }
    __syncthreads();

    uint32_t sbXN = smem_u32(sXN), sbW1 = smem_u32(sW1);
    uint32_t sbF1 = smem_u32(sF1), sbW2 = smem_u32(sW2);
    int a_r = (lane & 15), a_k = ((lane >> 4) << 3);
    int b_r = (lane & 7) + ((lane >> 4) << 3), b_k = (((lane >> 3) & 1) << 3);

    {
        int wm = wid & 3, wn = wid >> 2;
        float acc[2][8][4];
#pragma unroll
        for (int i = 0; i < 2; i++)
#pragma unroll
            for (int j = 0; j < 8; j++)
#pragma unroll
                for (int q = 0; q < 4; q++) acc[i][j][q] = 0.f;
#pragma unroll
        for (int k16 = 0; k16 < 4; k16++) {
            int kb = k16 * 16;
            uint32_t bh[8][2];
#pragma unroll
            for (int np = 0; np < 4; np++) {
                uint32_t boff = (uint32_t)((wn * 64 + np * 16 + b_r) * 72 + kb + b_k) * 2;
                ldm_x4(bh[np * 2][0], bh[np * 2][1], bh[np * 2 + 1][0], bh[np * 2 + 1][1], sbW1 + boff);
            }
#pragma unroll
            for (int mt2 = 0; mt2 < 2; mt2++) {
                uint32_t aoff = (uint32_t)((wm * 32 + mt2 * 16 + a_r) * 72 + kb + a_k) * 2;
                uint32_t ah[4];
                ldm_x4(ah[0], ah[1], ah[2], ah[3], sbXN + aoff);
#pragma unroll
                for (int ntl = 0; ntl < 8; ntl++) mma16816(acc[mt2][ntl], ah, bh[ntl]);
            }
        }
#pragma unroll
        for (int mt2 = 0; mt2 < 2; mt2++) {
#pragma unroll
            for (int ntl = 0; ntl < 8; ntl++) {
                int col = wn * 64 + ntl * 8 + (lane & 3) * 2;
                int r1 = wm * 32 + mt2 * 16 + (lane >> 2), r2 = r1 + 8;
                float b0 = sFB1[col], b1 = sFB1[col + 1];
                float c0 = fmaxf(acc[mt2][ntl][0] + b0, 0.f);
                float c1 = fmaxf(acc[mt2][ntl][1] + b1, 0.f);
                float c2 = fmaxf(acc[mt2][ntl][2] + b0, 0.f);
                float c3 = fmaxf(acc[mt2][ntl][3] + b1, 0.f);
                *(__nv_bfloat162*)(sF1 + r1 * 264 + col) = __float22bfloat162_rn(make_float2(c0, c1));
                *(__nv_bfloat162*)(sF1 + r2 * 264 + col) = __float22bfloat162_rn(make_float2(c2, c3));
            }
        }
    }
    __syncthreads();

    {
        int wm2 = wid & 7, wn2 = wid >> 3;
        float acc2[4][4];
#pragma unroll
        for (int j = 0; j < 4; j++)
#pragma unroll
            for (int q = 0; q < 4; q++) acc2[j][q] = 0.f;
#pragma unroll
        for (int k16 = 0; k16 < 16; k16++) {
            int kb = k16 * 16;
            uint32_t bh[4][2];
#pragma unroll
            for (int np = 0; np < 2; np++) {
                uint32_t boff = (uint32_t)((wn2 * 32 + np * 16 + b_r) * 264 + kb + b_k) * 2;
                ldm_x4(bh[np * 2][0], bh[np * 2][1], bh[np * 2 + 1][0], bh[np * 2 + 1][1], sbW2 + boff);
            }
            uint32_t aoff = (uint32_t)((wm2 * 16 + a_r) * 264 + kb + a_k) * 2;
            uint32_t ah[4];
            ldm_x4(ah[0], ah[1], ah[2], ah[3], sbF1 + aoff);
#pragma unroll
            for (int ntl = 0; ntl < 4; ntl++) mma16816(acc2[ntl], ah, bh[ntl]);
        }
        __half* ghf = g_hf + (size_t)e * BTOK * DDIM + (size_t)r0 * 64;
#pragma unroll
        for (int ntl = 0; ntl < 4; ntl++) {
            int col = wn2 * 32 + ntl * 8 + (lane & 3) * 2;
            float b0 = sFB2[col], b1 = sFB2[col + 1];
            float l0 = sLS2[col], l1 = sLS2[col + 1];
#pragma unroll
            for (int half = 0; half < 2; half++) {
                int r = wm2 * 16 + (lane >> 2) + half * 8;
                if (r0 + r < rows_e) {
                    float w = sWGT[r];
                    float v0 = w * (sXS[r * 64 + col]     + l0 * (acc2[ntl][half * 2]     + b0));
                    float v1 = w * (sXS[r * 64 + col + 1] + l1 * (acc2[ntl][half * 2 + 1] + b1));
                    *(__half2*)(ghf + (size_t)r * 64 + col) = __floats2half2_rn(v0, v1);
                }
            }
        }
    }
}

// ---------------- K3: warp-MMA fp16 proj GEMM, cp.async double-buffered (R15 proven) ----------------
#define KC 32
#define SSTRIDE 40
#define PJ_TILE_BYTES 10240
#define PJ_STAGE_BYTES (2 * PJ_TILE_BYTES)
#define PJ_SMEM (2 * PJ_STAGE_BYTES)

__global__ void __launch_bounds__(256, 2) k_proj_mma() {
    int e  = blockIdx.y >> 6;
    int mt = blockIdx.y & 63;
    int nt = blockIdx.x;
    int cnt = g_cnt[e];
    int row0 = mt * 128;
    if (row0 >= cnt) return;

    extern __shared__ char smb[];
    uint32_t sb0 = smem_u32(smb);

    int t = threadIdx.x;
    int wid = t >> 5, lane = t & 31;
    int wm = wid & 1, wn = wid >> 1;

    const __half* Af = g_hf + (size_t)(e * BTOK) * DDIM;
    const __half* Bf = g_pwh + (size_t)e * DDIM * DDIM + (size_t)(nt * 128) * DDIM;

    float acc[4][4][4];
#pragma unroll
    for (int i = 0; i < 4; i++)
#pragma unroll
        for (int j = 0; j < 4; j++)
#pragma unroll
            for (int q = 0; q < 4; q++) acc[i][j][q] = 0.f;

    int rw0 = t >> 2, q0 = t & 3;
    int rw1 = rw0 + 64, q1 = q0;
    bool v0 = (row0 + rw0) < cnt, v1 = (row0 + rw1) < cnt;
    int ra0 = v0 ? (row0 + rw0) : 0, ra1 = v1 ? (row0 + rw1) : 0;
    int sz0 = v0 ? 16 : 0, sz1 = v1 ? 16 : 0;
    uint32_t off0 = (uint32_t)(rw0 * 5 + q0) * 16;
    uint32_t off1 = (uint32_t)(rw1 * 5 + q1) * 16;

#define PJ_ISSUE(cc, stg) do { \
        int k0 = (cc) * KC; \
        uint32_t db = sb0 + (uint32_t)(stg) * PJ_STAGE_BYTES; \
        size_t ea0 = (size_t)ra0 * DDIM + k0 + q0 * 8; \
        size_t ea1 = (size_t)ra1 * DDIM + k0 + q1 * 8; \
        size_t eb0 = (size_t)rw0 * DDIM + k0 + q0 * 8; \
        size_t eb1 = (size_t)rw1 * DDIM + k0 + q1 * 8; \
        cpa16(db + off0,                 Af + ea0, sz0); \
        cpa16(db + off1,                 Af + ea1, sz1); \
        cpa16(db + PJ_TILE_BYTES + off0, Bf + eb0, 16); \
        cpa16(db + PJ_TILE_BYTES + off1, Bf + eb1, 16); \
    } while (0)

    int a_r = (lane & 15), a_k = ((lane >> 4) << 3);
    int b_r = (lane & 7) + ((lane >> 4) << 3), b_k = (((lane >> 3) & 1) << 3);

    const int NCHUNK = DDIM / KC;
    PJ_ISSUE(0, 0); CPA_COMMIT();
    PJ_ISSUE(1, 1); CPA_COMMIT();

    for (int c = 0; c < NCHUNK; c++) {
        CPA_WAIT1();
        __syncthreads();
        int stg = c & 1;
        uint32_t base = sb0 + (uint32_t)stg * PJ_STAGE_BYTES;
        uint32_t sA = base, sB = base + PJ_TILE_BYTES;

#pragma unroll
        for (int k16 = 0; k16 < 2; k16++) {
            int kb = k16 * 16;
            uint32_t bh[4][2];
#pragma unroll
            for (int np = 0; np < 2; np++) {
                uint32_t boff = (uint32_t)((wn * 32 + np * 16 + b_r) * SSTRIDE + kb + b_k) * 2;
                ldm_x4(bh[np * 2][0], bh[np * 2][1], bh[np * 2 + 1][0], bh[np * 2 + 1][1], sB + boff);
            }
#pragma unroll
            for (int mt2 = 0; mt2 < 4; mt2++) {
                uint32_t aoff = (uint32_t)((wm * 64 + mt2 * 16 + a_r) * SSTRIDE + kb + a_k) * 2;
                uint32_t ah[4];
                ldm_x4(ah[0], ah[1], ah[2], ah[3], sA + aoff);
#pragma unroll
                for (int ntl = 0; ntl < 4; ntl++)
                    mma16816h(acc[mt2][ntl], ah, bh[ntl]);
            }
        }
        __syncthreads();
        if (c + 2 < NCHUNK) PJ_ISSUE(c + 2, stg);
        CPA_COMMIT();
    }

    const float SCL = 1.f / 64.f;
    int lrow = lane >> 2, lcol = (lane & 3) * 2;
    __half* Ybase = g_y + (size_t)(e * BTOK) * DDIM;
#pragma unroll
    for (int mt2 = 0; mt2 < 4; mt2++) {
        int rbase = row0 + wm * 64 + mt2 * 16;
        int r1 = rbase + lrow, r2 = rbase + 8 + lrow;
#pragma unroll
        for (int ntl = 0; ntl < 4; ntl++) {
            int col = nt * 128 + wn * 32 + ntl * 8 + lcol;
            if (r1 < cnt) {
                *(__half2*)&Ybase[(size_t)r1 * DDIM + col] =
                    __floats2half2_rn(acc[mt2][ntl][0] * SCL, acc[mt2][ntl][1] * SCL);
            }
            if (r2 < cnt) {
                *(__half2*)&Ybase[(size_t)r2 * DDIM + col] =
                    __floats2half2_rn(acc[mt2][ntl][2] * SCL, acc[mt2][ntl][3] * SCL);
            }
        }
    }
}

// ---------------- K4: combine (+bias) + aux/load tail, 4 elems/thread ----------------
__global__ void k_combine(const float* __restrict__ pb, float* __restrict__ out,
                          long long out_size) {
    long long idx = (long long)blockIdx.x * 256 + threadIdx.x;
    const long long TOT4 = (long long)BTOK * DDIM / 4;
    if (idx < TOT4) {
        int b = (int)(idx / (DDIM / 4));
        int d = (int)(idx % (DDIM / 4)) * 4;
        int s0 = g_slot[2 * b], s1 = g_slot[2 * b + 1];
        int e0 = g_tope[2 * b], e1 = g_tope[2 * b + 1];
        float w0 = g_topw[2 * b], w1 = g_topw[2 * b + 1];
        const __half2* y0 = (const __half2*)(g_y + (size_t)s0 * DDIM + d);
        const __half2* y1 = (const __half2*)(g_y + (size_t)s1 * DDIM + d);
        float2 a0 = __half22float2(y0[0]), a1 = __half22float2(y0[1]);
        float2 b0 = __half22float2(y1[0]), b1 = __half22float2(y1[1]);
        float4 p0 = *(const float4*)(pb + (size_t)e0 * DDIM + d);
        float4 p1 = *(const float4*)(pb + (size_t)e1 * DDIM + d);
        float4 r;
        r.x = a0.x + b0.x + w0 * p0.x + w1 * p1.x;
        r.y = a0.y + b0.y + w0 * p0.y + w1 * p1.y;
        r.z = a1.x + b1.x + w0 * p0.z + w1 * p1.z;
        r.w = a1.y + b1.y + w0 * p0.w + w1 * p1.w;
        *(float4*)(out + idx * 4) = r;
    }
    if (idx == 0) {
        const long long TOT = (long long)BTOK * DDIM;
        if (out_size >= TOT + 5) {
            out[TOT] = 0.f;
#pragma unroll
            for (int e = 0; e < NEXP; e++) out[TOT + 1 + e] = (float)g_cnt[e];
        }
    }
}

// ---------------- host launcher ----------------
extern "C" void kernel_launch(void* const* d_in, const int* in_sizes, int n_in,
                              void* d_out, int out_size) {
    const float* x    = (const float*)d_in[0];
    const float* gw1  = (const float*)d_in[1];
    const float* gb1  = (const float*)d_in[2];
    const float* gw2  = (const float*)d_in[3];
    const float* gb2  = (const float*)d_in[4];
    const float* pos  = (const float*)d_in[5];
    const float* n1g  = (const float*)d_in[6];
    const float* ipw  = (const float*)d_in[7];
    const float* ipb  = (const float*)d_in[8];
    const float* opw  = (const float*)d_in[9];
    const float* opb  = (const float*)d_in[10];
    const float* ls1  = (const float*)d_in[11];
    const float* n2g  = (const float*)d_in[12];
    const float* fw1  = (const float*)d_in[13];
    const float* fb1  = (const float*)d_in[14];
    const float* fw2  = (const float*)d_in[15];
    const float* fb2  = (const float*)d_in[16];
    const float* ls2  = (const float*)d_in[17];
    const float* pw   = (const float*)d_in[18];
    const float* pb   = (const float*)d_in[19];
    float* out = (float*)d_out;

    cudaFuncSetAttribute(k_att, cudaFuncAttributeMaxDynamicSharedMemorySize, T_TOT);
    cudaFuncSetAttribute(k_ffn, cudaFuncAttributeMaxDynamicSharedMemorySize, F_TOT);
    cudaFuncSetAttribute(k_proj_mma, cudaFuncAttributeMaxDynamicSharedMemorySize, PJ_SMEM);

    k_init<<<1, 32>>>();
    k_pre<<<PRE_TOT_BLKS, 256>>>(x, gw1, gb1, gw2, gb2, pw, fw1, fw2, ipw, opw);
    k_att<<<dim3((BTOK + AT_TOK - 1) / AT_TOK, NEXP), 256, T_TOT>>>(x, pos, n1g, ipb, opb, ls1);
    k_ffn<<<dim3(BTOK * NCH / 128, NEXP), 512, F_TOT>>>(n2g, fb1, fb2, ls2);
    k_proj_mma<<<dim3(DDIM / 128, NEXP * 64), 256, PJ_SMEM>>>();
    long long tot4 = (long long)BTOK * DDIM / 4;
    k_combine<<<(unsigned)((tot4 + 255) / 256), 256>>>(pb, out, (long long)out_size);
}